// round 16
// baseline (speedup 1.0000x reference)
#include <cuda_runtime.h>
#include <math.h>
#include <stdint.h>

#define BB   128
#define TT   64
#define SS   40
#define DD   256
#define HH   256
#define NG   1024
#define BT   (BB*TT)

#define OG_OFF   0
#define FAKE_OFF 256
#define DEC_OFF  512
#define GEN_OFF  (DEC_OFF + BT*DD)
#define STS_OFF  (GEN_OFF + BT*DD)
#define LBL_OFF  (STS_OFF + BB*TT)

__device__ float g_v[BT*DD];
__device__ float g_xg[TT*BB*NG];     // [t][b][u*4+gate]
__device__ float g_h1[BT*HH];
__device__ float g_h2[BT*HH];
__device__ float g_wh[BT*HH];
__device__ float g_bar[BT*DD];
__device__ float g_wz[BT*64];
__device__ float g_ez[BB*64];
__device__ float g_t1[256*1024];
__device__ float g_t2[256*512];
__device__ float g_hwork[2*4*HH*32]; // [phase][bg][u][b32]
__device__ unsigned int g_flag[128]; // [bg*32 + hg] = last completed step+1

__device__ __forceinline__ void fma2(float2& d, float2 a, float2 b)
{
    unsigned long long dd = *(unsigned long long*)&d;
    unsigned long long aa = *(unsigned long long*)&a;
    unsigned long long bb = *(unsigned long long*)&b;
    asm("fma.rn.f32x2 %0, %1, %2, %0;" : "+l"(dd) : "l"(aa), "l"(bb));
    d = *(float2*)&dd;
}
__device__ __forceinline__ float fsig(float x) { return __fdividef(1.f, 1.f + __expf(-x)); }
__device__ __forceinline__ float ftanh(float x) { return fmaf(2.f, __fdividef(1.f, 1.f + __expf(-2.f*x)), -1.f); }
__device__ __forceinline__ void red2(float2& v, int off)
{
    v.x += __shfl_xor_sync(0xffffffffu, v.x, off);
    v.y += __shfl_xor_sync(0xffffffffu, v.y, off);
}
__device__ __forceinline__ uint32_t to_tf32(float v)
{
    uint32_t u;
    asm("cvt.rna.tf32.f32 %0, %1;" : "=r"(u) : "f"(v));
    return u;
}

// ---------------- embed: 4 rows/block, float4 gathers (R14-validated) ----------------
__global__ void embed_kernel(const int* __restrict__ seqs, const float* __restrict__ emb)
{
    __shared__ int idx[4][SS];
    const int bv0 = blockIdx.x * 4;
    const int tid = threadIdx.x;
    const int sub = tid >> 6;
    const int dq  = tid & 63;
    if (tid < 4*SS) idx[tid / SS][tid % SS] = seqs[bv0*SS + tid];
    __syncthreads();
    float4 acc = make_float4(0.f, 0.f, 0.f, 0.f);
#pragma unroll 8
    for (int s = 0; s < SS; s++) {
        const float4* row = (const float4*)&emb[(size_t)idx[sub][s]*DD];
        float4 e = row[dq];
        acc.x += fmaxf(e.x, 0.f);
        acc.y += fmaxf(e.y, 0.f);
        acc.z += fmaxf(e.z, 0.f);
        acc.w += fmaxf(e.w, 0.f);
    }
    ((float4*)&g_v[(size_t)(bv0 + sub)*DD])[dq] = acc;
}

// ---------------- TF32 tensor-core GEMM: 128x64 tile (R12-validated) ----------------
// C = act(A @ W^T + bias [+bias2]);  M mult 128, N mult 64, K mult 32
// rows >= Msplit (if Msplit>0) come from A2 instead of A (same lda)
// mode 0: C[m*N+n]; mode 1 (N=1024): C[(t*BB+b)*NG + (n&255)*4 + (n>>8)]
// mode 1 block(0,0) also resets the lstm arrival flags.
__global__ void __launch_bounds__(256)
gemm_tf32_kernel(const float* __restrict__ A, const float* __restrict__ A2,
                 int Msplit, int lda,
                 const float* __restrict__ W, int ldw,
                 const float* __restrict__ bias, const float* __restrict__ bias2,
                 float* __restrict__ C, int K, int N, int mode, int act)
{
    __shared__ uint32_t As[32][136];
    __shared__ uint32_t Bs[32][72];
    const int tid  = threadIdx.x;
    const int lane = tid & 31;
    const int warp = tid >> 5;
    const int wm = warp >> 1, wn = warp & 1;
    const int grp = lane >> 2, tg = lane & 3;
    const int m0 = blockIdx.y*128, n0 = blockIdx.x*64;

    if (mode == 1 && blockIdx.x == 0 && blockIdx.y == 0 && tid < 128)
        g_flag[tid] = 0u;

    const int arow = tid & 127, aq0 = (tid >> 7) * 4;
    const int brow = tid & 63,  bq0 = tid >> 6;
    const float* Abase = (Msplit && m0 >= Msplit)
        ? A2 + (size_t)(m0 - Msplit + arow)*lda
        : A  + (size_t)(m0 + arow)*lda;
    const float* Wload = W + (size_t)(n0 + brow)*ldw;

    float c[2][4][4];
#pragma unroll
    for (int i = 0; i < 2; i++)
#pragma unroll
        for (int j = 0; j < 4; j++)
#pragma unroll
            for (int e = 0; e < 4; e++) c[i][j][e] = 0.f;

    for (int k0 = 0; k0 < K; k0 += 32) {
        if (k0) __syncthreads();
#pragma unroll
        for (int q = 0; q < 4; q++) {
            float4 v = *(const float4*)(Abase + k0 + (aq0 + q)*4);
            As[(aq0+q)*4+0][arow] = to_tf32(v.x);
            As[(aq0+q)*4+1][arow] = to_tf32(v.y);
            As[(aq0+q)*4+2][arow] = to_tf32(v.z);
            As[(aq0+q)*4+3][arow] = to_tf32(v.w);
        }
#pragma unroll
        for (int q = 0; q < 2; q++) {
            int bq = bq0 + q*4;
            float4 v = *(const float4*)(Wload + k0 + bq*4);
            Bs[bq*4+0][brow] = to_tf32(v.x);
            Bs[bq*4+1][brow] = to_tf32(v.y);
            Bs[bq*4+2][brow] = to_tf32(v.z);
            Bs[bq*4+3][brow] = to_tf32(v.w);
        }
        __syncthreads();

#pragma unroll
        for (int kk = 0; kk < 4; kk++) {
            const int kb = kk*8;
            uint32_t a[2][4], b[4][2];
#pragma unroll
            for (int mt = 0; mt < 2; mt++) {
                int mr = wm*32 + mt*16 + grp;
                a[mt][0] = As[kb+tg  ][mr];
                a[mt][1] = As[kb+tg  ][mr+8];
                a[mt][2] = As[kb+tg+4][mr];
                a[mt][3] = As[kb+tg+4][mr+8];
            }
#pragma unroll
            for (int nt = 0; nt < 4; nt++) {
                int nc = wn*32 + nt*8 + grp;
                b[nt][0] = Bs[kb+tg  ][nc];
                b[nt][1] = Bs[kb+tg+4][nc];
            }
#pragma unroll
            for (int mt = 0; mt < 2; mt++)
#pragma unroll
                for (int nt = 0; nt < 4; nt++) {
                    asm("mma.sync.aligned.m16n8k8.row.col.f32.tf32.tf32.f32 "
                        "{%0,%1,%2,%3}, {%4,%5,%6,%7}, {%8,%9}, {%0,%1,%2,%3};"
                        : "+f"(c[mt][nt][0]), "+f"(c[mt][nt][1]),
                          "+f"(c[mt][nt][2]), "+f"(c[mt][nt][3])
                        : "r"(a[mt][0]), "r"(a[mt][1]), "r"(a[mt][2]), "r"(a[mt][3]),
                          "r"(b[nt][0]), "r"(b[nt][1]));
                }
        }
    }

#pragma unroll
    for (int mt = 0; mt < 2; mt++) {
#pragma unroll
        for (int nt = 0; nt < 4; nt++) {
#pragma unroll
            for (int half = 0; half < 2; half++) {
                int m = m0 + wm*32 + mt*16 + grp + half*8;
                int n = n0 + wn*32 + nt*8 + tg*2;
                float v0 = c[mt][nt][half*2+0];
                float v1 = c[mt][nt][half*2+1];
                if (bias)  { v0 += bias[n];  v1 += bias[n+1]; }
                if (bias2) { v0 += bias2[n]; v1 += bias2[n+1]; }
                if (act)   { v0 = fmaxf(v0, 0.f); v1 = fmaxf(v1, 0.f); }
                if (mode == 0) {
                    C[(size_t)m*N + n]   = v0;
                    C[(size_t)m*N + n+1] = v1;
                } else {
                    int b = m >> 6, t = m & 63;
                    float* dst = C + ((size_t)t*BB + b)*NG;
                    dst[(n & 255)*4 + (n >> 8)]         = v0;
                    dst[((n+1) & 255)*4 + ((n+1) >> 8)] = v1;
                }
            }
        }
    }
}

// ---------------- persistent LSTM: flag-arrival barrier (this round's change) ----------------
__global__ void __launch_bounds__(256, 1)
lstm_kernel(const float* __restrict__ xg, const float* __restrict__ Whh,
            float* __restrict__ h_all)
{
    __shared__ float h_sm[256*36];
    const int tid = threadIdx.x;
    const int lane = tid & 31;
    const int ks  = lane & 7;
    const int bpg = lane >> 3;
    const int rg  = tid >> 5;
    const int hg  = blockIdx.x >> 2, bg = blockIdx.x & 3;
    const int u0  = hg*8, u = u0 + rg;
    const int bb  = lane;
    const int b   = bg*32 + bb;

    float wr[4][32];
    {
        float* wtmp = h_sm;
        for (int c = tid; c < 2048; c += 256) {
            int ro = c >> 6, jq = c & 63;
            *(float4*)&wtmp[ro*256 + jq*4] =
                *(const float4*)&Whh[(size_t)((ro>>3)*HH + u0 + (ro&7))*HH + jq*4];
        }
        __syncthreads();
#pragma unroll
        for (int g = 0; g < 4; g++)
#pragma unroll
            for (int jj = 0; jj < 32; jj++)
                wr[g][jj] = wtmp[(g*8 + rg)*256 + jj*8 + ks];
        __syncthreads();
    }
    for (int i = tid; i < 256*36; i += 256) h_sm[i] = 0.f;
    float cst = 0.f;
    __syncthreads();

    float4 xgv = *(const float4*)&xg[((size_t)0*BB + b)*NG + u*4];

    for (int t = 0; t < TT; t++) {
        float2 acc[4][4];
#pragma unroll
        for (int g = 0; g < 4; g++)
#pragma unroll
            for (int p = 0; p < 4; p++) acc[g][p] = make_float2(0.f, 0.f);

#pragma unroll
        for (int jj = 0; jj < 32; jj++) {
            const float* hp = &h_sm[(jj*8 + ks)*36 + bpg*8];
            float4 h0 = *(const float4*)hp;
            float4 h1 = *(const float4*)(hp + 4);
            float2 hp0 = make_float2(h0.x, h0.y), hp1 = make_float2(h0.z, h0.w);
            float2 hp2 = make_float2(h1.x, h1.y), hp3 = make_float2(h1.z, h1.w);
#pragma unroll
            for (int g = 0; g < 4; g++) {
                float2 w2 = make_float2(wr[g][jj], wr[g][jj]);
                fma2(acc[g][0], w2, hp0); fma2(acc[g][1], w2, hp1);
                fma2(acc[g][2], w2, hp2); fma2(acc[g][3], w2, hp3);
            }
        }
#pragma unroll
        for (int off = 1; off <= 4; off <<= 1)
#pragma unroll
            for (int g = 0; g < 4; g++) {
                red2(acc[g][0], off); red2(acc[g][1], off);
                red2(acc[g][2], off); red2(acc[g][3], off);
            }
        float gv[4];
#pragma unroll
        for (int g = 0; g < 4; g++) {
            float2 lo = (ks & 2) ? acc[g][1] : acc[g][0];
            float2 hi = (ks & 2) ? acc[g][3] : acc[g][2];
            float2 s  = (ks & 4) ? hi : lo;
            gv[g] = (ks & 1) ? s.y : s.x;
        }
        float gi = gv[0] + xgv.x, gf = gv[1] + xgv.y;
        float gg = gv[2] + xgv.z, go = gv[3] + xgv.w;
        cst = fsig(gf)*cst + fsig(gi)*ftanh(gg);
        float h = fsig(go)*ftanh(cst);

        h_all[((size_t)b*TT + t)*HH + u] = h;
        float* hw = g_hwork + (size_t)((t & 1)*4 + bg)*(HH*32);
        __stcg(&hw[u*32 + bb], h);

        if (t == TT-1) break;

        xgv = *(const float4*)&xg[((size_t)(t+1)*BB + b)*NG + u*4];

        // flag-arrival barrier: publish own step, wait on all 32 producers in bg
        __syncthreads();
        if (tid == 0) {
            __threadfence();
            __stcg(&g_flag[bg*32 + hg], (unsigned)(t + 1));
        }
        if (tid < 32) {
            volatile unsigned* f = (volatile unsigned*)&g_flag[bg*32 + tid];
            while (*f < (unsigned)(t + 1)) { }
        }
        __syncthreads();

        const float4* src = (const float4*)hw;
#pragma unroll
        for (int r = 0; r < 8; r++) {
            int c = tid + 256*r;
            float4 v = __ldcg(src + c);
            *(float4*)&h_sm[(c >> 3)*36 + (c & 7)*4] = v;
        }
        __syncthreads();
    }
}

// ---------------- attention finalize + tail (merged, R12-validated) ----------------
__global__ void attn_tail_kernel(const float* __restrict__ W2, const float* __restrict__ b2,
                                 const float* __restrict__ sts, const int* __restrict__ label,
                                 float* __restrict__ out)
{
    const int b = blockIdx.x >> 6, row = blockIdx.x & 63;
    const int tid = threadIdx.x;

    if (row == 0) {
        float val = g_v[(size_t)b*TT*DD + tid];
        size_t o = (size_t)b*TT*DD + tid;
        g_bar[o] = val; out[DEC_OFF + o] = val; out[GEN_OFF + o] = val;
        if (tid < TT) out[STS_OFF + b*TT + tid] = sts[b*TT + tid];
        if (tid == 0) out[LBL_OFF + b] = (float)label[b];
        return;
    }

    const int t = row - 1;
    __shared__ float z1[64];
    __shared__ float a01[2];
    if (tid < 64) z1[tid] = tanhf(g_ez[b*64 + tid] + g_wz[((size_t)b*TT + t)*64 + tid]);
    __syncthreads();
    if (tid < 32) {
        float x0 = z1[tid], x1 = z1[tid + 32];
        float s0 = x0*W2[tid]    + x1*W2[tid+32];
        float s1 = x0*W2[64+tid] + x1*W2[96+tid];
#pragma unroll
        for (int off = 16; off; off >>= 1) {
            s0 += __shfl_xor_sync(0xffffffffu, s0, off);
            s1 += __shfl_xor_sync(0xffffffffu, s1, off);
        }
        if (tid == 0) {
            s0 += b2[0]; s1 += b2[1];
            float m = fmaxf(s0, s1);
            float e0 = expf(s0-m), e1 = expf(s1-m);
            float inv = 1.f/(e0+e1);
            a01[0] = e0*inv; a01[1] = e1*inv;
        }
    }
    __syncthreads();
    float e = g_v[(size_t)b*TT*DD + tid];
    float w = g_wh[((size_t)b*TT + t)*HH + tid];
    float bv = e*a01[0] + w*a01[1];
    size_t o = ((size_t)b*TT + row)*DD + tid;
    g_bar[o] = bv; out[DEC_OFF + o] = bv; out[GEN_OFF + o] = bv;
}

// ---------------- warp-per-output FC head (M=256, N=2) ----------------
__global__ void fc_kernel(const float* __restrict__ A, int lda,
                          const float* __restrict__ W, int ldw,
                          const float* __restrict__ bias,
                          float* __restrict__ C, int ldc, int M, int N, int K)
{
    int gw = (blockIdx.x*blockDim.x + threadIdx.x) >> 5;
    int lane = threadIdx.x & 31;
    if (gw >= M*N) return;
    int m = gw / N, n = gw % N;
    const float* a = A + (size_t)m*lda;
    const float* w = W + (size_t)n*ldw;
    float acc = 0.f;
    for (int k = lane*4; k < K; k += 128) {
        float4 av = *(const float4*)(a+k);
        float4 wv = *(const float4*)(w+k);
        acc += av.x*wv.x + av.y*wv.y + av.z*wv.z + av.w*wv.w;
    }
#pragma unroll
    for (int off = 16; off; off >>= 1) acc += __shfl_xor_sync(0xffffffffu, acc, off);
    if (lane == 0) C[(size_t)m*ldc + n] = acc + bias[n];
}

extern "C" void kernel_launch(void* const* d_in, const int* in_sizes, int n_in,
                              void* d_out, int out_size)
{
    (void)in_sizes; (void)n_in; (void)out_size;
    const int*   seqs  = (const int*)  d_in[0];
    const float* sts   = (const float*)d_in[3];
    const int*   label = (const int*)  d_in[5];
    const float* emb   = (const float*)d_in[6];
    const float* W_ih  = (const float*)d_in[7];
    const float* W_hh  = (const float*)d_in[8];
    const float* b_ih  = (const float*)d_in[9];
    const float* b_hh  = (const float*)d_in[10];
    const float* Whk   = (const float*)d_in[11];
    const float* bhk   = (const float*)d_in[12];
    const float* W1    = (const float*)d_in[13];
    const float* b1    = (const float*)d_in[14];
    const float* W2    = (const float*)d_in[15];
    const float* b2    = (const float*)d_in[16];
    const float* C1W   = (const float*)d_in[17];
    const float* C1b   = (const float*)d_in[18];
    const float* C2W   = (const float*)d_in[19];
    const float* C2b   = (const float*)d_in[20];
    const float* CoW   = (const float*)d_in[21];
    const float* Cob   = (const float*)d_in[22];
    float* out = (float*)d_out;

    float *p_v, *p_xg, *p_h1, *p_h2, *p_wh, *p_bar, *p_wz, *p_ez, *p_t1, *p_t2;
    cudaGetSymbolAddress((void**)&p_v, g_v);
    cudaGetSymbolAddress((void**)&p_xg, g_xg);
    cudaGetSymbolAddress((void**)&p_h1, g_h1);
    cudaGetSymbolAddress((void**)&p_h2, g_h2);
    cudaGetSymbolAddress((void**)&p_wh, g_wh);
    cudaGetSymbolAddress((void**)&p_bar, g_bar);
    cudaGetSymbolAddress((void**)&p_wz, g_wz);
    cudaGetSymbolAddress((void**)&p_ez, g_ez);
    cudaGetSymbolAddress((void**)&p_t1, g_t1);
    cudaGetSymbolAddress((void**)&p_t2, g_t2);

    embed_kernel<<<BT/4, 256>>>(seqs, emb);

    // xg1 = v @ W_ih^T + b_ih + b_hh  (tf32, resets lstm flags)
    gemm_tf32_kernel<<<dim3(NG/64, BT/128), 256>>>(p_v, nullptr, 0, DD, W_ih, DD,
                                                   b_ih, b_hh, p_xg, DD, NG, 1, 0);
    lstm_kernel<<<128, 256>>>(p_xg, W_hh, p_h1);

    // wh = h1 @ Whk^T + bhk
    gemm_tf32_kernel<<<dim3(HH/64, BT/128), 256>>>(p_h1, nullptr, 0, HH, Whk, HH,
                                                   bhk, nullptr, p_wh, HH, HH, 0, 0);
    // wz = wh @ W1[:,256:]^T
    gemm_tf32_kernel<<<dim3(1, BT/128), 256>>>(p_wh, nullptr, 0, HH, W1 + 256, 512,
                                               nullptr, nullptr, p_wz, HH, 64, 0, 0);
    // ez = v[:,0,:] @ W1[:,:256]^T + b1
    gemm_tf32_kernel<<<dim3(1, 1), 256>>>(p_v, nullptr, 0, TT*DD, W1, 512,
                                          b1, nullptr, p_ez, DD, 64, 0, 0);
    attn_tail_kernel<<<BT, 256>>>(W2, b2, sts, label, out);

    // xg2 = bar_v @ W_ih^T + b_ih + b_hh  (tf32, resets lstm flags)
    gemm_tf32_kernel<<<dim3(NG/64, BT/128), 256>>>(p_bar, nullptr, 0, DD, W_ih, DD,
                                                   b_ih, b_hh, p_xg, DD, NG, 1, 0);
    lstm_kernel<<<128, 256>>>(p_xg, W_hh, p_h2);

    // classify both branches batched: rows 0-127 = h1[t=63], 128-255 = h2[t=63]
    gemm_tf32_kernel<<<dim3(1024/64, 2), 256>>>(p_h1 + 63*HH, p_h2 + 63*HH, 128, TT*HH,
                                                C1W, HH, C1b, nullptr, p_t1, HH, 1024, 0, 1);
    gemm_tf32_kernel<<<dim3(512/64, 2), 256>>>(p_t1, nullptr, 0, 1024, C2W, 1024,
                                               C2b, nullptr, p_t2, 1024, 512, 0, 1);
    fc_kernel<<<64, 256>>>(p_t2, 512, CoW, 512, Cob, out, 2, 256, 2, 512);
}

// round 17
// speedup vs baseline: 1.6030x; 1.6030x over previous
#include <cuda_runtime.h>
#include <math.h>
#include <stdint.h>

#define BB   128
#define TT   64
#define SS   40
#define DD   256
#define HH   256
#define NG   1024
#define BT   (BB*TT)

#define OG_OFF   0
#define FAKE_OFF 256
#define DEC_OFF  512
#define GEN_OFF  (DEC_OFF + BT*DD)
#define STS_OFF  (GEN_OFF + BT*DD)
#define LBL_OFF  (STS_OFF + BB*TT)

__device__ float g_v[BT*DD];
__device__ float g_xg[TT*BB*NG];     // [t][b][u*4+gate]
__device__ float g_h1[BT*HH];
__device__ float g_h2[BT*HH];
__device__ float g_wh[BT*HH];
__device__ float g_bar[BT*DD];
__device__ float g_wz[BT*64];
__device__ float g_ez[BB*64];
__device__ float g_t1[256*1024];
__device__ float g_t2[256*512];
__device__ float g_hwork[2*4*HH*32]; // [phase][bg][u][b32]
__device__ unsigned int g_barrier[4*64];  // counter bg at [bg*64]: 256B stride, own LTS

__device__ __forceinline__ void fma2(float2& d, float2 a, float2 b)
{
    unsigned long long dd = *(unsigned long long*)&d;
    unsigned long long aa = *(unsigned long long*)&a;
    unsigned long long bb = *(unsigned long long*)&b;
    asm("fma.rn.f32x2 %0, %1, %2, %0;" : "+l"(dd) : "l"(aa), "l"(bb));
    d = *(float2*)&dd;
}
__device__ __forceinline__ float fsig(float x) { return __fdividef(1.f, 1.f + __expf(-x)); }
__device__ __forceinline__ float ftanh(float x) { return fmaf(2.f, __fdividef(1.f, 1.f + __expf(-2.f*x)), -1.f); }
__device__ __forceinline__ void red2(float2& v, int off)
{
    v.x += __shfl_xor_sync(0xffffffffu, v.x, off);
    v.y += __shfl_xor_sync(0xffffffffu, v.y, off);
}
__device__ __forceinline__ uint32_t to_tf32(float v)
{
    uint32_t u;
    asm("cvt.rna.tf32.f32 %0, %1;" : "=r"(u) : "f"(v));
    return u;
}

// ---------------- embed: 4 rows/block, float4 gathers (R14-validated) ----------------
__global__ void embed_kernel(const int* __restrict__ seqs, const float* __restrict__ emb)
{
    __shared__ int idx[4][SS];
    const int bv0 = blockIdx.x * 4;
    const int tid = threadIdx.x;
    const int sub = tid >> 6;
    const int dq  = tid & 63;
    if (tid < 4*SS) idx[tid / SS][tid % SS] = seqs[bv0*SS + tid];
    __syncthreads();
    float4 acc = make_float4(0.f, 0.f, 0.f, 0.f);
#pragma unroll 8
    for (int s = 0; s < SS; s++) {
        const float4* row = (const float4*)&emb[(size_t)idx[sub][s]*DD];
        float4 e = row[dq];
        acc.x += fmaxf(e.x, 0.f);
        acc.y += fmaxf(e.y, 0.f);
        acc.z += fmaxf(e.z, 0.f);
        acc.w += fmaxf(e.w, 0.f);
    }
    ((float4*)&g_v[(size_t)(bv0 + sub)*DD])[dq] = acc;
}

// ---------------- TF32 tensor-core GEMM: 128x64 tile (R12-validated) ----------------
// C = act(A @ W^T + bias [+bias2]);  M mult 128, N mult 64, K mult 32
// rows >= Msplit (if Msplit>0) come from A2 instead of A (same lda)
// mode 0: C[m*N+n]; mode 1 (N=1024): C[(t*BB+b)*NG + (n&255)*4 + (n>>8)]
// mode 1 block(0,0) also resets the lstm barrier counters.
__global__ void __launch_bounds__(256)
gemm_tf32_kernel(const float* __restrict__ A, const float* __restrict__ A2,
                 int Msplit, int lda,
                 const float* __restrict__ W, int ldw,
                 const float* __restrict__ bias, const float* __restrict__ bias2,
                 float* __restrict__ C, int K, int N, int mode, int act)
{
    __shared__ uint32_t As[32][136];
    __shared__ uint32_t Bs[32][72];
    const int tid  = threadIdx.x;
    const int lane = tid & 31;
    const int warp = tid >> 5;
    const int wm = warp >> 1, wn = warp & 1;
    const int grp = lane >> 2, tg = lane & 3;
    const int m0 = blockIdx.y*128, n0 = blockIdx.x*64;

    if (mode == 1 && blockIdx.x == 0 && blockIdx.y == 0 && tid < 4)
        g_barrier[tid*64] = 0u;

    const int arow = tid & 127, aq0 = (tid >> 7) * 4;
    const int brow = tid & 63,  bq0 = tid >> 6;
    const float* Abase = (Msplit && m0 >= Msplit)
        ? A2 + (size_t)(m0 - Msplit + arow)*lda
        : A  + (size_t)(m0 + arow)*lda;
    const float* Wload = W + (size_t)(n0 + brow)*ldw;

    float c[2][4][4];
#pragma unroll
    for (int i = 0; i < 2; i++)
#pragma unroll
        for (int j = 0; j < 4; j++)
#pragma unroll
            for (int e = 0; e < 4; e++) c[i][j][e] = 0.f;

    for (int k0 = 0; k0 < K; k0 += 32) {
        if (k0) __syncthreads();
#pragma unroll
        for (int q = 0; q < 4; q++) {
            float4 v = *(const float4*)(Abase + k0 + (aq0 + q)*4);
            As[(aq0+q)*4+0][arow] = to_tf32(v.x);
            As[(aq0+q)*4+1][arow] = to_tf32(v.y);
            As[(aq0+q)*4+2][arow] = to_tf32(v.z);
            As[(aq0+q)*4+3][arow] = to_tf32(v.w);
        }
#pragma unroll
        for (int q = 0; q < 2; q++) {
            int bq = bq0 + q*4;
            float4 v = *(const float4*)(Wload + k0 + bq*4);
            Bs[bq*4+0][brow] = to_tf32(v.x);
            Bs[bq*4+1][brow] = to_tf32(v.y);
            Bs[bq*4+2][brow] = to_tf32(v.z);
            Bs[bq*4+3][brow] = to_tf32(v.w);
        }
        __syncthreads();

#pragma unroll
        for (int kk = 0; kk < 4; kk++) {
            const int kb = kk*8;
            uint32_t a[2][4], b[4][2];
#pragma unroll
            for (int mt = 0; mt < 2; mt++) {
                int mr = wm*32 + mt*16 + grp;
                a[mt][0] = As[kb+tg  ][mr];
                a[mt][1] = As[kb+tg  ][mr+8];
                a[mt][2] = As[kb+tg+4][mr];
                a[mt][3] = As[kb+tg+4][mr+8];
            }
#pragma unroll
            for (int nt = 0; nt < 4; nt++) {
                int nc = wn*32 + nt*8 + grp;
                b[nt][0] = Bs[kb+tg  ][nc];
                b[nt][1] = Bs[kb+tg+4][nc];
            }
#pragma unroll
            for (int mt = 0; mt < 2; mt++)
#pragma unroll
                for (int nt = 0; nt < 4; nt++) {
                    asm("mma.sync.aligned.m16n8k8.row.col.f32.tf32.tf32.f32 "
                        "{%0,%1,%2,%3}, {%4,%5,%6,%7}, {%8,%9}, {%0,%1,%2,%3};"
                        : "+f"(c[mt][nt][0]), "+f"(c[mt][nt][1]),
                          "+f"(c[mt][nt][2]), "+f"(c[mt][nt][3])
                        : "r"(a[mt][0]), "r"(a[mt][1]), "r"(a[mt][2]), "r"(a[mt][3]),
                          "r"(b[nt][0]), "r"(b[nt][1]));
                }
        }
    }

#pragma unroll
    for (int mt = 0; mt < 2; mt++) {
#pragma unroll
        for (int nt = 0; nt < 4; nt++) {
#pragma unroll
            for (int half = 0; half < 2; half++) {
                int m = m0 + wm*32 + mt*16 + grp + half*8;
                int n = n0 + wn*32 + nt*8 + tg*2;
                float v0 = c[mt][nt][half*2+0];
                float v1 = c[mt][nt][half*2+1];
                if (bias)  { v0 += bias[n];  v1 += bias[n+1]; }
                if (bias2) { v0 += bias2[n]; v1 += bias2[n+1]; }
                if (act)   { v0 = fmaxf(v0, 0.f); v1 = fmaxf(v1, 0.f); }
                if (mode == 0) {
                    C[(size_t)m*N + n]   = v0;
                    C[(size_t)m*N + n+1] = v1;
                } else {
                    int b = m >> 6, t = m & 63;
                    float* dst = C + ((size_t)t*BB + b)*NG;
                    dst[(n & 255)*4 + (n >> 8)]         = v0;
                    dst[((n+1) & 255)*4 + ((n+1) >> 8)] = v1;
                }
            }
        }
    }
}

// ---------------- persistent LSTM (R10/R14-validated; padded barrier counters) ----------------
__global__ void __launch_bounds__(256, 1)
lstm_kernel(const float* __restrict__ xg, const float* __restrict__ Whh,
            float* __restrict__ h_all)
{
    __shared__ float h_sm[256*36];
    const int tid = threadIdx.x;
    const int lane = tid & 31;
    const int ks  = lane & 7;
    const int bpg = lane >> 3;
    const int rg  = tid >> 5;
    const int hg  = blockIdx.x >> 2, bg = blockIdx.x & 3;
    const int u0  = hg*8, u = u0 + rg;
    const int bb  = lane;
    const int b   = bg*32 + bb;

    float wr[4][32];
    {
        float* wtmp = h_sm;
        for (int c = tid; c < 2048; c += 256) {
            int ro = c >> 6, jq = c & 63;
            *(float4*)&wtmp[ro*256 + jq*4] =
                *(const float4*)&Whh[(size_t)((ro>>3)*HH + u0 + (ro&7))*HH + jq*4];
        }
        __syncthreads();
#pragma unroll
        for (int g = 0; g < 4; g++)
#pragma unroll
            for (int jj = 0; jj < 32; jj++)
                wr[g][jj] = wtmp[(g*8 + rg)*256 + jj*8 + ks];
        __syncthreads();
    }
    for (int i = tid; i < 256*36; i += 256) h_sm[i] = 0.f;
    float cst = 0.f;
    unsigned target = 32;
    __syncthreads();

    float4 xgv = *(const float4*)&xg[((size_t)0*BB + b)*NG + u*4];

    for (int t = 0; t < TT; t++) {
        float2 acc[4][4];
#pragma unroll
        for (int g = 0; g < 4; g++)
#pragma unroll
            for (int p = 0; p < 4; p++) acc[g][p] = make_float2(0.f, 0.f);

#pragma unroll
        for (int jj = 0; jj < 32; jj++) {
            const float* hp = &h_sm[(jj*8 + ks)*36 + bpg*8];
            float4 h0 = *(const float4*)hp;
            float4 h1 = *(const float4*)(hp + 4);
            float2 hp0 = make_float2(h0.x, h0.y), hp1 = make_float2(h0.z, h0.w);
            float2 hp2 = make_float2(h1.x, h1.y), hp3 = make_float2(h1.z, h1.w);
#pragma unroll
            for (int g = 0; g < 4; g++) {
                float2 w2 = make_float2(wr[g][jj], wr[g][jj]);
                fma2(acc[g][0], w2, hp0); fma2(acc[g][1], w2, hp1);
                fma2(acc[g][2], w2, hp2); fma2(acc[g][3], w2, hp3);
            }
        }
#pragma unroll
        for (int off = 1; off <= 4; off <<= 1)
#pragma unroll
            for (int g = 0; g < 4; g++) {
                red2(acc[g][0], off); red2(acc[g][1], off);
                red2(acc[g][2], off); red2(acc[g][3], off);
            }
        float gv[4];
#pragma unroll
        for (int g = 0; g < 4; g++) {
            float2 lo = (ks & 2) ? acc[g][1] : acc[g][0];
            float2 hi = (ks & 2) ? acc[g][3] : acc[g][2];
            float2 s  = (ks & 4) ? hi : lo;
            gv[g] = (ks & 1) ? s.y : s.x;
        }
        float gi = gv[0] + xgv.x, gf = gv[1] + xgv.y;
        float gg = gv[2] + xgv.z, go = gv[3] + xgv.w;
        cst = fsig(gf)*cst + fsig(gi)*ftanh(gg);
        float h = fsig(go)*ftanh(cst);

        h_all[((size_t)b*TT + t)*HH + u] = h;
        float* hw = g_hwork + (size_t)((t & 1)*4 + bg)*(HH*32);
        __stcg(&hw[u*32 + bb], h);

        if (t == TT-1) break;

        xgv = *(const float4*)&xg[((size_t)(t+1)*BB + b)*NG + u*4];

        __syncthreads();
        if (tid == 0) {
            __threadfence();
            atomicAdd(&g_barrier[bg*64], 1u);
            volatile unsigned* barp = (volatile unsigned*)&g_barrier[bg*64];
            while (*barp < target) { }
        }
        __syncthreads();
        target += 32;

        const float4* src = (const float4*)hw;
#pragma unroll
        for (int r = 0; r < 8; r++) {
            int c = tid + 256*r;
            float4 v = __ldcg(src + c);
            *(float4*)&h_sm[(c >> 3)*36 + (c & 7)*4] = v;
        }
        __syncthreads();
    }
}

// ---------------- attention finalize + tail (merged, R12-validated) ----------------
__global__ void attn_tail_kernel(const float* __restrict__ W2, const float* __restrict__ b2,
                                 const float* __restrict__ sts, const int* __restrict__ label,
                                 float* __restrict__ out)
{
    const int b = blockIdx.x >> 6, row = blockIdx.x & 63;
    const int tid = threadIdx.x;

    if (row == 0) {
        float val = g_v[(size_t)b*TT*DD + tid];
        size_t o = (size_t)b*TT*DD + tid;
        g_bar[o] = val; out[DEC_OFF + o] = val; out[GEN_OFF + o] = val;
        if (tid < TT) out[STS_OFF + b*TT + tid] = sts[b*TT + tid];
        if (tid == 0) out[LBL_OFF + b] = (float)label[b];
        return;
    }

    const int t = row - 1;
    __shared__ float z1[64];
    __shared__ float a01[2];
    if (tid < 64) z1[tid] = tanhf(g_ez[b*64 + tid] + g_wz[((size_t)b*TT + t)*64 + tid]);
    __syncthreads();
    if (tid < 32) {
        float x0 = z1[tid], x1 = z1[tid + 32];
        float s0 = x0*W2[tid]    + x1*W2[tid+32];
        float s1 = x0*W2[64+tid] + x1*W2[96+tid];
#pragma unroll
        for (int off = 16; off; off >>= 1) {
            s0 += __shfl_xor_sync(0xffffffffu, s0, off);
            s1 += __shfl_xor_sync(0xffffffffu, s1, off);
        }
        if (tid == 0) {
            s0 += b2[0]; s1 += b2[1];
            float m = fmaxf(s0, s1);
            float e0 = expf(s0-m), e1 = expf(s1-m);
            float inv = 1.f/(e0+e1);
            a01[0] = e0*inv; a01[1] = e1*inv;
        }
    }
    __syncthreads();
    float e = g_v[(size_t)b*TT*DD + tid];
    float w = g_wh[((size_t)b*TT + t)*HH + tid];
    float bv = e*a01[0] + w*a01[1];
    size_t o = ((size_t)b*TT + row)*DD + tid;
    g_bar[o] = bv; out[DEC_OFF + o] = bv; out[GEN_OFF + o] = bv;
}

// ---------------- warp-per-output FC head (M=256, N=2) ----------------
__global__ void fc_kernel(const float* __restrict__ A, int lda,
                          const float* __restrict__ W, int ldw,
                          const float* __restrict__ bias,
                          float* __restrict__ C, int ldc, int M, int N, int K)
{
    int gw = (blockIdx.x*blockDim.x + threadIdx.x) >> 5;
    int lane = threadIdx.x & 31;
    if (gw >= M*N) return;
    int m = gw / N, n = gw % N;
    const float* a = A + (size_t)m*lda;
    const float* w = W + (size_t)n*ldw;
    float acc = 0.f;
    for (int k = lane*4; k < K; k += 128) {
        float4 av = *(const float4*)(a+k);
        float4 wv = *(const float4*)(w+k);
        acc += av.x*wv.x + av.y*wv.y + av.z*wv.z + av.w*wv.w;
    }
#pragma unroll
    for (int off = 16; off; off >>= 1) acc += __shfl_xor_sync(0xffffffffu, acc, off);
    if (lane == 0) C[(size_t)m*ldc + n] = acc + bias[n];
}

extern "C" void kernel_launch(void* const* d_in, const int* in_sizes, int n_in,
                              void* d_out, int out_size)
{
    (void)in_sizes; (void)n_in; (void)out_size;
    const int*   seqs  = (const int*)  d_in[0];
    const float* sts   = (const float*)d_in[3];
    const int*   label = (const int*)  d_in[5];
    const float* emb   = (const float*)d_in[6];
    const float* W_ih  = (const float*)d_in[7];
    const float* W_hh  = (const float*)d_in[8];
    const float* b_ih  = (const float*)d_in[9];
    const float* b_hh  = (const float*)d_in[10];
    const float* Whk   = (const float*)d_in[11];
    const float* bhk   = (const float*)d_in[12];
    const float* W1    = (const float*)d_in[13];
    const float* b1    = (const float*)d_in[14];
    const float* W2    = (const float*)d_in[15];
    const float* b2    = (const float*)d_in[16];
    const float* C1W   = (const float*)d_in[17];
    const float* C1b   = (const float*)d_in[18];
    const float* C2W   = (const float*)d_in[19];
    const float* C2b   = (const float*)d_in[20];
    const float* CoW   = (const float*)d_in[21];
    const float* Cob   = (const float*)d_in[22];
    float* out = (float*)d_out;

    float *p_v, *p_xg, *p_h1, *p_h2, *p_wh, *p_bar, *p_wz, *p_ez, *p_t1, *p_t2;
    cudaGetSymbolAddress((void**)&p_v, g_v);
    cudaGetSymbolAddress((void**)&p_xg, g_xg);
    cudaGetSymbolAddress((void**)&p_h1, g_h1);
    cudaGetSymbolAddress((void**)&p_h2, g_h2);
    cudaGetSymbolAddress((void**)&p_wh, g_wh);
    cudaGetSymbolAddress((void**)&p_bar, g_bar);
    cudaGetSymbolAddress((void**)&p_wz, g_wz);
    cudaGetSymbolAddress((void**)&p_ez, g_ez);
    cudaGetSymbolAddress((void**)&p_t1, g_t1);
    cudaGetSymbolAddress((void**)&p_t2, g_t2);

    embed_kernel<<<BT/4, 256>>>(seqs, emb);

    // xg1 = v @ W_ih^T + b_ih + b_hh  (tf32, resets lstm barriers)
    gemm_tf32_kernel<<<dim3(NG/64, BT/128), 256>>>(p_v, nullptr, 0, DD, W_ih, DD,
                                                   b_ih, b_hh, p_xg, DD, NG, 1, 0);
    lstm_kernel<<<128, 256>>>(p_xg, W_hh, p_h1);

    // wh = h1 @ Whk^T + bhk
    gemm_tf32_kernel<<<dim3(HH/64, BT/128), 256>>>(p_h1, nullptr, 0, HH, Whk, HH,
                                                   bhk, nullptr, p_wh, HH, HH, 0, 0);
    // wz = wh @ W1[:,256:]^T
    gemm_tf32_kernel<<<dim3(1, BT/128), 256>>>(p_wh, nullptr, 0, HH, W1 + 256, 512,
                                               nullptr, nullptr, p_wz, HH, 64, 0, 0);
    // ez = v[:,0,:] @ W1[:,:256]^T + b1
    gemm_tf32_kernel<<<dim3(1, 1), 256>>>(p_v, nullptr, 0, TT*DD, W1, 512,
                                          b1, nullptr, p_ez, DD, 64, 0, 0);
    attn_tail_kernel<<<BT, 256>>>(W2, b2, sts, label, out);

    // xg2 = bar_v @ W_ih^T + b_ih + b_hh  (tf32, resets lstm barriers)
    gemm_tf32_kernel<<<dim3(NG/64, BT/128), 256>>>(p_bar, nullptr, 0, DD, W_ih, DD,
                                                   b_ih, b_hh, p_xg, DD, NG, 1, 0);
    lstm_kernel<<<128, 256>>>(p_xg, W_hh, p_h2);

    // classify both branches batched: rows 0-127 = h1[t=63], 128-255 = h2[t=63]
    gemm_tf32_kernel<<<dim3(1024/64, 2), 256>>>(p_h1 + 63*HH, p_h2 + 63*HH, 128, TT*HH,
                                                C1W, HH, C1b, nullptr, p_t1, HH, 1024, 0, 1);
    gemm_tf32_kernel<<<dim3(512/64, 2), 256>>>(p_t1, nullptr, 0, 1024, C2W, 1024,
                                               C2b, nullptr, p_t2, 1024, 512, 0, 1);
    fc_kernel<<<64, 256>>>(p_t2, 512, CoW, 512, Cob, out, 2, 256, 2, 512);
}